// round 6
// baseline (speedup 1.0000x reference)
#include <cuda_runtime.h>
#include <math.h>

#define Bsz 64
#define Pn  2048
#define Ln  512
#define Hn  8
#define NC  16      // row-chunks per batch in flash pass
#define RPB (Pn/NC) // 128 rows per flash block
#define TR  8       // rows per smem stage

typedef unsigned long long u64;

// ---------------- static scratch (no allocation) ----------------
__device__ float  g_qn [Bsz*Ln];
__device__ float  g_Q  [Bsz*Ln];
__device__ __align__(16) float g_gu [Bsz*Hn*Ln];
__device__ float  g_Sgu[Bsz*Hn];
__device__ float  g_bu [Bsz*Hn];
__device__ float4 g_A4 [(size_t)Bsz*NC*Hn*(Ln/4)];   // partial accumulators
__device__ float4 g_msb[Bsz*NC*Hn];                  // (M, S, c, 0) per partial
__device__ float2 g_MS [Bsz*Hn];                     // final (M, 1/S)

// ---------------- packed f32x2 helpers ----------------
__device__ __forceinline__ u64 pk2(float lo, float hi) {
    u64 r; asm("mov.b64 %0, {%1,%2};" : "=l"(r) : "f"(lo), "f"(hi)); return r;
}
__device__ __forceinline__ void upk2(u64 v, float& lo, float& hi) {
    asm("mov.b64 {%0,%1}, %2;" : "=f"(lo), "=f"(hi) : "l"(v));
}
__device__ __forceinline__ u64 fma2(u64 a, u64 b, u64 c) {
    u64 r; asm("fma.rn.f32x2 %0, %1, %2, %3;" : "=l"(r) : "l"(a), "l"(b), "l"(c)); return r;
}
__device__ __forceinline__ u64 mul2(u64 a, u64 b) {
    u64 r; asm("mul.rn.f32x2 %0, %1, %2;" : "=l"(r) : "l"(a), "l"(b)); return r;
}
__device__ __forceinline__ u64 add2(u64 a, u64 b) {
    u64 r; asm("add.rn.f32x2 %0, %1, %2;" : "=l"(r) : "l"(a), "l"(b)); return r;
}

// ---------------- cp.async helpers ----------------
__device__ __forceinline__ void cpasync16(void* smem, const void* g) {
    unsigned s = (unsigned)__cvta_generic_to_shared(smem);
    asm volatile("cp.async.cg.shared.global [%0], [%1], 16;" :: "r"(s), "l"(g));
}
#define CP_COMMIT()  asm volatile("cp.async.commit_group;")
#define CP_WAIT(N)   asm volatile("cp.async.wait_group %0;" :: "n"(N))

// ---------------- K1: LN of query rows + init ----------------
__global__ void k1_ln_init(const float* __restrict__ xt,
                           const float* __restrict__ g, const float* __restrict__ b_,
                           const float* __restrict__ resb, float* __restrict__ outctx)
{
    int b = blockIdx.x, t = threadIdx.x;
    __shared__ float xs[Ln];
    __shared__ float red[16];
    __shared__ float stats[2];
    float2 v = ((const float2*)xt)[b*(Ln/2) + t];
    xs[2*t] = v.x; xs[2*t+1] = v.y;
    float s1 = v.x + v.y, s2 = v.x*v.x + v.y*v.y;
    #pragma unroll
    for (int o = 16; o; o >>= 1) {
        s1 += __shfl_xor_sync(~0u, s1, o);
        s2 += __shfl_xor_sync(~0u, s2, o);
    }
    int w = t >> 5, lane = t & 31;
    if (!lane) { red[w] = s1; red[8+w] = s2; }
    __syncthreads();
    if (!t) {
        float a = 0.f, c = 0.f;
        #pragma unroll
        for (int i = 0; i < 8; i++) { a += red[i]; c += red[8+i]; }
        float mean = a * (1.f/Ln);
        float var  = c * (1.f/Ln) - mean*mean;
        stats[0] = mean; stats[1] = rsqrtf(var + 1e-5f);
    }
    __syncthreads();
    float mean = stats[0], rstd = stats[1];
    #pragma unroll
    for (int l = t; l < Ln; l += 256) {
        g_qn[b*Ln + l]   = (xs[l] - mean) * rstd * g[l] + b_[l];
        outctx[b*Ln + l] = resb[l];
        g_Q[b*Ln + l]    = 0.f;
    }
    if (t < 8) { g_Sgu[b*8 + t] = 0.f; g_bu[b*8 + t] = 0.f; }
}

// ---------------- K2: split-K GEMMs: Q = qn@W_q ; out += x_trafic@res_W ----------------
__global__ void k2_gemm(const float* __restrict__ xt,
                        const float* __restrict__ Wq, const float* __restrict__ Wr,
                        float* __restrict__ outctx)
{
    int kc = blockIdx.x, bg = blockIdx.y, mat = blockIdx.z;
    const float* X = mat ? xt : g_qn;
    const float* W = mat ? Wr : Wq;
    float* OUT     = mat ? outctx : g_Q;
    __shared__ float xsm[8*64];
    int t = threadIdx.x;
    xsm[t]       = X[(bg*8 + (t>>6))*Ln       + kc*64 + (t&63)];
    xsm[t + 256] = X[(bg*8 + ((t+256)>>6))*Ln + kc*64 + (t&63)];
    __syncthreads();
    float acc[16];
    #pragma unroll
    for (int i = 0; i < 16; i++) acc[i] = 0.f;
    int d0 = t, d1 = t + 256;
    #pragma unroll 4
    for (int kk = 0; kk < 64; kk++) {
        float w0 = W[(kc*64 + kk)*Ln + d0];
        float w1 = W[(kc*64 + kk)*Ln + d1];
        #pragma unroll
        for (int bb = 0; bb < 8; bb++) {
            float x = xsm[bb*64 + kk];
            acc[2*bb]   += x * w0;
            acc[2*bb+1] += x * w1;
        }
    }
    #pragma unroll
    for (int bb = 0; bb < 8; bb++) {
        atomicAdd(&OUT[(bg*8+bb)*Ln + d0], acc[2*bb]);
        atomicAdd(&OUT[(bg*8+bb)*Ln + d1], acc[2*bb+1]);
    }
}

// ---------------- K3: tiled mini-GEMM  u[b,h,l] = (1/8) Wk_row(l,head h) . Q(b,head h) ----------------
__global__ void k3_u(const float* __restrict__ Wk,
                     const float* __restrict__ lng, const float* __restrict__ lnb)
{
    int lt = blockIdx.x, bg = blockIdx.y;
    int l0 = lt*16, b0 = bg*4;
    int t = threadIdx.x;
    int l = t & 15, h = t >> 4;
    __shared__ float4 Wks[16*128];   // 16 rows x 512 floats
    __shared__ float4 Qs [4*128];    // 4 rows x 512 floats

    const float4* wsrc = (const float4*)(Wk + (size_t)l0*Ln);
    #pragma unroll
    for (int k = 0; k < 16; k++) Wks[t + k*128] = wsrc[t + k*128];
    const float4* qsrc = (const float4*)(g_Q + (size_t)b0*Ln);
    #pragma unroll
    for (int k = 0; k < 4; k++) Qs[t + k*128] = qsrc[t + k*128];
    __syncthreads();

    float4 wr[16];
    #pragma unroll
    for (int k = 0; k < 16; k++) wr[k] = Wks[l*128 + h*16 + k];

    float gl = lng[l0 + l], bl = lnb[l0 + l];

    #pragma unroll
    for (int bb = 0; bb < 4; bb++) {
        float4 a4 = make_float4(0.f, 0.f, 0.f, 0.f);
        #pragma unroll
        for (int k = 0; k < 16; k++) {
            float4 q = Qs[bb*128 + h*16 + k];
            a4.x = fmaf(wr[k].x, q.x, a4.x);
            a4.y = fmaf(wr[k].y, q.y, a4.y);
            a4.z = fmaf(wr[k].z, q.z, a4.z);
            a4.w = fmaf(wr[k].w, q.w, a4.w);
        }
        float acc = (a4.x + a4.y) + (a4.z + a4.w);
        float u = acc * 0.125f;     // includes 1/sqrt(D_K)
        float guv = gl * u;
        g_gu[((size_t)(b0+bb)*Hn + h)*Ln + l0 + l] = guv;
        float sS = guv, sB = bl * u;
        #pragma unroll
        for (int o = 8; o; o >>= 1) {
            sS += __shfl_xor_sync(~0u, sS, o);
            sB += __shfl_xor_sync(~0u, sB, o);
        }
        if (l == 0) {
            atomicAdd(&g_Sgu[(b0+bb)*Hn + h], sS);
            atomicAdd(&g_bu [(b0+bb)*Hn + h], sB);
        }
    }
}

// ---------------- K4 v4: flash pass, race-free pipeline, 4 warps x 2 heads ----------------
__global__ void __launch_bounds__(128, 5) k4_flash(
    const float* __restrict__ xd, float* __restrict__ attn_scores)
{
    int b = blockIdx.x, chunk = blockIdx.y;
    int t = threadIdx.x, w = t >> 5, lane = t & 31;   // warp w handles heads w and w+4
    __shared__ ulonglong2 xs[2][TR*128];              // 2 x 16KB stages
    __shared__ float2 rowstat[TR];

    const int h0 = w, h1 = w + 4;

    u64 gu0[8], gu1[8];
    {
        const ulonglong2* p0 = (const ulonglong2*)(g_gu + (size_t)(b*Hn + h0)*Ln);
        const ulonglong2* p1 = (const ulonglong2*)(g_gu + (size_t)(b*Hn + h1)*Ln);
        #pragma unroll
        for (int j = 0; j < 4; j++) {
            ulonglong2 v0 = p0[j*32 + lane];
            ulonglong2 v1 = p1[j*32 + lane];
            gu0[2*j] = v0.x; gu0[2*j+1] = v0.y;
            gu1[2*j] = v1.x; gu1[2*j+1] = v1.y;
        }
    }
    float Sgu0 = g_Sgu[b*Hn + h0], bu0 = g_bu[b*Hn + h0];
    float Sgu1 = g_Sgu[b*Hn + h1], bu1 = g_bu[b*Hn + h1];

    float M0 = -1e30f, S0 = 0.f, c0 = 0.f;
    float M1 = -1e30f, S1 = 0.f, c1 = 0.f;
    u64 A0[8], A1[8];
    #pragma unroll
    for (int j = 0; j < 8; j++) { A0[j] = 0ull; A1[j] = 0ull; }

    const size_t rowbase = (size_t)b*Pn + (size_t)chunk*RPB;
    float* sc0 = attn_scores + (size_t)(b*Hn + h0)*Pn + chunk*RPB;
    float* sc1 = attn_scores + (size_t)(b*Hn + h1)*Pn + chunk*RPB;

    // prefetch tile 0
    {
        const ulonglong2* src = (const ulonglong2*)(xd + rowbase*Ln);
        #pragma unroll
        for (int k = 0; k < 8; k++) {
            int idx = t + k*128;
            cpasync16(&xs[0][idx], &src[idx]);
        }
        CP_COMMIT();
    }

    int st = 0;
    for (int tile = 0; tile < RPB/TR; tile++) {
        CP_WAIT(0);          // current tile landed (only one group ever pending here)
        __syncthreads();     // data visible to all AND all warps done reading buffer st^1

        // NOW it is safe to overwrite st^1: issue next prefetch (overlaps stats+compute)
        if (tile + 1 < RPB/TR) {
            const ulonglong2* src = (const ulonglong2*)(xd + (rowbase + (size_t)(tile+1)*TR)*Ln);
            #pragma unroll
            for (int k = 0; k < 8; k++) {
                int idx = t + k*128;
                cpasync16(&xs[st^1][idx], &src[idx]);
            }
            CP_COMMIT();
        }

        // ---- stats phase: warp w does rows w and w+4 ----
        #pragma unroll
        for (int rr = 0; rr < 2; rr++) {
            int r = w + rr*4;
            const ulonglong2* xr = &xs[st][r*128];
            u64 s1 = 0ull, s2 = 0ull;
            #pragma unroll
            for (int j = 0; j < 4; j++) {
                ulonglong2 v = xr[j*32 + lane];
                s1 = add2(s1, v.x); s1 = add2(s1, v.y);
                s2 = fma2(v.x, v.x, s2); s2 = fma2(v.y, v.y, s2);
            }
            float l1, hh1, l2, hh2;
            upk2(s1, l1, hh1); upk2(s2, l2, hh2);
            float f1 = l1 + hh1, f2 = l2 + hh2;
            float s  = (lane & 1) ? f2 : f1;
            float so = (lane & 1) ? f1 : f2;
            s += __shfl_xor_sync(~0u, so, 1);
            s += __shfl_xor_sync(~0u, s, 2);
            s += __shfl_xor_sync(~0u, s, 4);
            s += __shfl_xor_sync(~0u, s, 8);
            s += __shfl_xor_sync(~0u, s, 16);
            float sum2 = __shfl_sync(~0u, s, 1);
            if (!lane) {
                float mean = s * (1.f/Ln);
                float var  = sum2 * (1.f/Ln) - mean*mean;
                rowstat[r] = make_float2(mean, rsqrtf(var + 1e-5f));
            }
        }
        __syncthreads();

        // ---- compute phase: each warp processes all 8 rows for its 2 heads ----
        #pragma unroll
        for (int r = 0; r < TR; r++) {
            ulonglong2 a2[4];
            const ulonglong2* xr = &xs[st][r*128];
            #pragma unroll
            for (int j = 0; j < 4; j++) a2[j] = xr[j*32 + lane];

            u64 d0 = 0ull, d1 = 0ull;
            #pragma unroll
            for (int j = 0; j < 4; j++) {
                d0 = fma2(a2[j].x, gu0[2*j],   d0);
                d0 = fma2(a2[j].y, gu0[2*j+1], d0);
                d1 = fma2(a2[j].x, gu1[2*j],   d1);
                d1 = fma2(a2[j].y, gu1[2*j+1], d1);
            }
            float l0f, h0f, l1f, h1f;
            upk2(d0, l0f, h0f); upk2(d1, l1f, h1f);
            float f0 = l0f + h0f, f1 = l1f + h1f;
            float s  = (lane & 1) ? f1 : f0;
            float so = (lane & 1) ? f0 : f1;
            s += __shfl_xor_sync(~0u, so, 1);
            s += __shfl_xor_sync(~0u, s, 2);
            s += __shfl_xor_sync(~0u, s, 4);
            s += __shfl_xor_sync(~0u, s, 8);
            s += __shfl_xor_sync(~0u, s, 16);
            float D0 = __shfl_sync(~0u, s, 0);
            float D1 = __shfl_sync(~0u, s, 1);

            float2 stt = rowstat[r];

            // head h0
            {
                float score = stt.y * (D0 - stt.x*Sgu0) + bu0;
                if (!lane) sc0[tile*TR + r] = score;
                float e;
                if (score > M0) {
                    float sc = __expf(M0 - score);
                    S0 *= sc; c0 *= sc;
                    u64 sc2 = pk2(sc, sc);
                    #pragma unroll
                    for (int k = 0; k < 8; k++) A0[k] = mul2(A0[k], sc2);
                    M0 = score; e = 1.f;
                } else {
                    e = __expf(score - M0);
                }
                S0 += e;
                float cf = e * stt.y;
                c0 += cf * stt.x;
                u64 cf2 = pk2(cf, cf);
                #pragma unroll
                for (int j = 0; j < 4; j++) {
                    A0[2*j]   = fma2(cf2, a2[j].x, A0[2*j]);
                    A0[2*j+1] = fma2(cf2, a2[j].y, A0[2*j+1]);
                }
            }
            // head h1
            {
                float score = stt.y * (D1 - stt.x*Sgu1) + bu1;
                if (!lane) sc1[tile*TR + r] = score;
                float e;
                if (score > M1) {
                    float sc = __expf(M1 - score);
                    S1 *= sc; c1 *= sc;
                    u64 sc2 = pk2(sc, sc);
                    #pragma unroll
                    for (int k = 0; k < 8; k++) A1[k] = mul2(A1[k], sc2);
                    M1 = score; e = 1.f;
                } else {
                    e = __expf(score - M1);
                }
                S1 += e;
                float cf = e * stt.y;
                c1 += cf * stt.x;
                u64 cf2 = pk2(cf, cf);
                #pragma unroll
                for (int j = 0; j < 4; j++) {
                    A1[2*j]   = fma2(cf2, a2[j].x, A1[2*j]);
                    A1[2*j+1] = fma2(cf2, a2[j].y, A1[2*j+1]);
                }
            }
        }
        st ^= 1;
    }

    // write partials for both heads
    {
        ulonglong2* p0 = (ulonglong2*)&g_A4[((size_t)(b*NC + chunk)*Hn + h0)*(Ln/4)];
        ulonglong2* p1 = (ulonglong2*)&g_A4[((size_t)(b*NC + chunk)*Hn + h1)*(Ln/4)];
        #pragma unroll
        for (int j = 0; j < 4; j++) {
            ulonglong2 v0; v0.x = A0[2*j]; v0.y = A0[2*j+1];
            ulonglong2 v1; v1.x = A1[2*j]; v1.y = A1[2*j+1];
            p0[j*32 + lane] = v0;
            p1[j*32 + lane] = v1;
        }
    }
    if (!lane) {
        g_msb[(b*NC + chunk)*Hn + h0] = make_float4(M0, S0, c0, 0.f);
        g_msb[(b*NC + chunk)*Hn + h1] = make_float4(M1, S1, c1, 0.f);
    }
}

// ---------------- K5: combine partials, wsum, ctx GEMV, add into out ----------------
__global__ void k5_reduce(const float* __restrict__ Wv,
                          const float* __restrict__ lng, const float* __restrict__ lnb,
                          float* __restrict__ outctx)
{
    int b = blockIdx.x, h = blockIdx.y;
    int t = threadIdx.x;   // 128 threads
    __shared__ float wsh[NC];
    __shared__ float sInvS, sC;
    __shared__ float ws[Ln];
    __shared__ float part[128];
    if (t == 0) {
        float Mg = -1e30f;
        #pragma unroll
        for (int i = 0; i < NC; i++) Mg = fmaxf(Mg, g_msb[(b*NC+i)*Hn + h].x);
        float Sg = 0.f, cg = 0.f;
        #pragma unroll
        for (int i = 0; i < NC; i++) {
            float4 m = g_msb[(b*NC+i)*Hn + h];
            float wgt = __expf(m.x - Mg);
            wsh[i] = wgt; Sg += wgt*m.y; cg += wgt*m.z;
        }
        sInvS = 1.f/Sg; sC = cg;
        g_MS[b*Hn + h] = make_float2(Mg, 1.f/Sg);
    }
    __syncthreads();
    float invS = sInvS, cg = sC;
    {
        int v = t;   // one float4 per thread: 128 x 4 = 512 floats = Ln
        float4 acc = make_float4(0.f, 0.f, 0.f, 0.f);
        for (int i = 0; i < NC; i++) {
            float4 a = g_A4[((size_t)(b*NC+i)*Hn + h)*(Ln/4) + v];
            float wgt = wsh[i];
            acc.x += wgt*a.x; acc.y += wgt*a.y; acc.z += wgt*a.z; acc.w += wgt*a.w;
        }
        float4 g4 = ((const float4*)lng)[v], b4 = ((const float4*)lnb)[v];
        ws[4*v+0] = g4.x*(acc.x - cg)*invS + b4.x;
        ws[4*v+1] = g4.y*(acc.y - cg)*invS + b4.y;
        ws[4*v+2] = g4.z*(acc.z - cg)*invS + b4.z;
        ws[4*v+3] = g4.w*(acc.w - cg)*invS + b4.w;
    }
    __syncthreads();
    int d = t & 63, half = t >> 6;
    float acc = 0.f;
    #pragma unroll 4
    for (int l = half*256; l < half*256 + 256; l++)
        acc += ws[l] * Wv[l*Ln + h*64 + d];
    part[t] = acc;
    __syncthreads();
    if (t < 64) outctx[b*Ln + h*64 + t] += part[t] + part[64 + t];
}

// ---------------- K6: normalize scores -> attn ----------------
__global__ void k6_norm(float* __restrict__ attn)
{
    int i  = blockIdx.x*256 + threadIdx.x;   // float4 index, 262144 total
    int bh = i >> 9;                         // 512 float4 per (b,h)
    float2 MS = g_MS[bh];
    float4 s = ((float4*)attn)[i];
    s.x = __expf(s.x - MS.x)*MS.y;
    s.y = __expf(s.y - MS.x)*MS.y;
    s.z = __expf(s.z - MS.x)*MS.y;
    s.w = __expf(s.w - MS.x)*MS.y;
    ((float4*)attn)[i] = s;
}

extern "C" void kernel_launch(void* const* d_in, const int* in_sizes, int n_in,
                              void* d_out, int out_size)
{
    const float* xt   = (const float*)d_in[0];
    const float* xd   = (const float*)d_in[1];
    // d_in[2] = x_known: unused by the reference computation
    const float* Wq   = (const float*)d_in[3];
    const float* Wk   = (const float*)d_in[4];
    const float* Wv   = (const float*)d_in[5];
    const float* lnqg = (const float*)d_in[6];
    const float* lnqb = (const float*)d_in[7];
    const float* lnkg = (const float*)d_in[8];
    const float* lnkb = (const float*)d_in[9];
    const float* Wr   = (const float*)d_in[10];
    const float* resb = (const float*)d_in[11];
    float* out  = (float*)d_out;
    float* attn = out + Bsz*Ln;   // context first, then attn (flattened tuple)

    k1_ln_init<<<Bsz, 256>>>(xt, lnqg, lnqb, resb, out);
    k2_gemm<<<dim3(8,8,2), 256>>>(xt, Wq, Wr, out);
    k3_u<<<dim3(32,16), 128>>>(Wk, lnkg, lnkb);
    k4_flash<<<dim3(Bsz, NC), 128>>>(xd, attn);
    k5_reduce<<<dim3(Bsz, Hn), 128>>>(Wv, lnkg, lnkb, out);
    k6_norm<<<1024, 256>>>(attn);
}